// round 13
// baseline (speedup 1.0000x reference)
#include <cuda_runtime.h>
#include <math.h>
#include <float.h>

#define MAXBT 1024
__device__ float g_loss_part[MAXBT];
__device__ float g_lossc_part[MAXBT];
__device__ unsigned int g_count;

typedef unsigned long long u64;

#define NBINS 64
#define XMINV (-4.0f)
#define BINW  (0.125f)
#define INVW  (8.0f)
#define NPTS  1024
#define MAXPAIR 544   // (1024 + 64 pad) / 2

__device__ __forceinline__ u64 pk2(float lo, float hi) {
    u64 r; asm("mov.b64 %0, {%1,%2};" : "=l"(r) : "f"(lo), "f"(hi)); return r;
}
__device__ __forceinline__ void upk2(float& lo, float& hi, u64 v) {
    asm("mov.b64 {%0,%1}, %2;" : "=f"(lo), "=f"(hi) : "l"(v));
}
__device__ __forceinline__ u64 ffma2(u64 a, u64 b, u64 c) {
    u64 d; asm("fma.rn.f32x2 %0, %1, %2, %3;" : "=l"(d) : "l"(a), "l"(b), "l"(c)); return d;
}

__device__ __forceinline__ float sl1(float a, float b) {
    float d = fabsf(a - b);
    return d < 1.0f ? 0.5f * d * d : d - 0.5f;
}

// Embed low 10 bits (pair id) into a float key's truncated mantissa.
// Keys are d' = tn - 2 x.t (signed); FMNMX orders them correctly.
__device__ __forceinline__ float embed10(float d, unsigned m2) {
    return __uint_as_float((__float_as_uint(d) & 0xFFFFFC00u) | m2);
}

__device__ __forceinline__ float blockReduceSum(float v, float* red) {
    #pragma unroll
    for (int o = 16; o > 0; o >>= 1)
        v += __shfl_down_sync(0xffffffffu, v, o);
    int lane = threadIdx.x & 31;
    int wid  = threadIdx.x >> 5;
    __syncthreads();
    if (lane == 0) red[wid] = v;
    __syncthreads();
    if (wid == 0) {
        v = (lane < (int)(blockDim.x >> 5)) ? red[lane] : 0.0f;
        #pragma unroll
        for (int o = 16; o > 0; o >>= 1)
            v += __shfl_down_sync(0xffffffffu, v, o);
    }
    return v;
}

// One CTA per (b,t) tile, 1024 threads. Targets counting-sorted into 64 bins
// by tx (bins padded to even counts with tn=1e30 sentinels), stored in the
// paired f32x2 layout:
//   sA[m2] = (-2tx_e, -2tx_o, -2ty_e, -2ty_o)
//   sB[m2] = (-2tz_e, -2tz_o,  tn_e,   tn_o)
// Preds bin-sorted too (warp-coherent windows). Each thread scans bins
// outward from its pred's bin, pruning with the exact bound
// dist^2 >= (tx - xx)^2 evaluated at bin edges.
__global__ __launch_bounds__(1024, 1)
void nn_loss_kernel(const float* __restrict__ X,
                    const float* __restrict__ T,
                    const float* __restrict__ W,
                    float* __restrict__ out,
                    int BT, int B)
{
    extern __shared__ char smem[];
    float4* sA  = (float4*)smem;                              //  8704 B
    float4* sB  = sA + MAXPAIR;                               //  8704 B
    float4* xs  = sB + MAXPAIR;                               // 16384 B (sorted preds)
    int* binSt  = (int*)(xs + NPTS);                          // 65
    int* curT   = binSt + 65;                                 // 64
    int* curP   = curT + NBINS;                               // 64
    float* red  = (float*)(curP + NBINS);                     // 32
    __shared__ int isLast;

    const int bt  = blockIdx.x;
    const int tid = threadIdx.x;
    const float* Xb = X + (size_t)bt * NPTS * 3;
    const float* Tb = T + (size_t)bt * NPTS * 3;

    // ---- Stage 1: load, zero histograms, init sentinels ----
    float t0 = Tb[tid * 3 + 0], t1 = Tb[tid * 3 + 1], t2 = Tb[tid * 3 + 2];
    float x0 = Xb[tid * 3 + 0], x1 = Xb[tid * 3 + 1], x2 = Xb[tid * 3 + 2];
    float tn = fmaf(t0, t0, fmaf(t1, t1, t2 * t2));
    float xn = fmaf(x0, x0, fmaf(x1, x1, x2 * x2));

    if (tid < 2 * NBINS) {      // zero both histogram/cursor arrays
        curT[tid & 63] = 0;     // tid 0..63 -> curT, 64..127 -> curP
        if (tid >= NBINS) curP[tid - NBINS] = 0;
        else curT[tid] = 0;
    }
    // sentinel init for padded pair slots
    for (int i = tid; i < MAXPAIR; i += NPTS) {
        sA[i] = make_float4(0.f, 0.f, 0.f, 0.f);
        sB[i] = make_float4(0.f, 0.f, 1e30f, 1e30f);
    }
    __syncthreads();

    int tbin = min(max((int)((t0 - XMINV) * INVW), 0), NBINS - 1);
    int pbin = min(max((int)((x0 - XMINV) * INVW), 0), NBINS - 1);
    atomicAdd(&curT[tbin], 1);
    atomicAdd(&curP[pbin], 1);
    __syncthreads();

    // ---- Stage 2: prefix sums (thread 0; even-rounded target bins) ----
    if (tid == 0) {
        int start = 0;
        #pragma unroll
        for (int b = 0; b < NBINS; ++b) {
            binSt[b] = start;
            start += (curT[b] + 1) & ~1;   // round bin size up to even
        }
        binSt[NBINS] = start;
        int ps = 0;
        #pragma unroll
        for (int b = 0; b < NBINS; ++b) {
            int c = curP[b];
            curP[b] = ps;      // pred cursor = start
            ps += c;
        }
        #pragma unroll
        for (int b = 0; b < NBINS; ++b) curT[b] = binSt[b];  // target cursor
    }
    __syncthreads();

    // ---- Stage 3: scatter ----
    {
        int slot = atomicAdd(&curT[tbin], 1);
        int m2 = slot >> 1, p = slot & 1;
        float* A  = (float*)&sA[m2];
        float* Bp = (float*)&sB[m2];
        A[p]      = -2.0f * t0;
        A[2 + p]  = -2.0f * t1;
        Bp[p]     = -2.0f * t2;
        Bp[2 + p] = tn;
        int ps = atomicAdd(&curP[pbin], 1);
        xs[ps] = make_float4(x0, x1, x2, xn);
    }
    __syncthreads();

    // ---- Stage 4: pruned scan (thread owns sorted pred slot tid) ----
    float4 xv = xs[tid];
    float xx = xv.x, xn2 = xv.w;
    u64 X0 = pk2(xv.x, xv.x), X1 = pk2(xv.y, xv.y), X2 = pk2(xv.z, xv.z);
    const ulonglong2* pA = (const ulonglong2*)sA;
    const ulonglong2* pB = (const ulonglong2*)sB;

    float bestE = FLT_MAX, bestO = FLT_MAX;

    int myb = min(max((int)((xx - XMINV) * INVW), 0), NBINS - 1);

    // scan helper (macro-ish lambda)
    auto scan_bin = [&](int b) {
        int m2s = binSt[b] >> 1;
        int m2e = binSt[b + 1] >> 1;
        for (int m2 = m2s; m2 < m2e; ++m2) {
            ulonglong2 a = pA[m2];
            ulonglong2 c = pB[m2];
            u64 dp = ffma2(X0, a.x, ffma2(X1, a.y, ffma2(X2, c.x, c.y)));
            float d0, d1;
            upk2(d0, d1, dp);
            bestE = fminf(bestE, embed10(d0, (unsigned)m2));
            bestO = fminf(bestO, embed10(d1, (unsigned)m2));
        }
    };

    scan_bin(myb);
    {
        int r = myb + 1, l = myb - 1;
        bool okR = r < NBINS, okL = l >= 0;
        while (okR || okL) {
            float bk = fminf(bestE, bestO);   // truncated best d' (<= true)
            if (okR) {
                float dx = fmaxf((XMINV + (float)r * BINW) - xx, 0.0f);
                if (fmaf(dx, dx, -xn2) > bk) okR = false;
                else { scan_bin(r); ++r; okR = r < NBINS; }
            }
            if (okL) {
                float dx = fmaxf(xx - (XMINV + (float)(l + 1) * BINW), 0.0f);
                if (fmaf(dx, dx, -xn2) > bk) okL = false;
                else { scan_bin(l); --l; okL = l >= 0; }
            }
        }
    }

    // decode winner, gather coords, smooth-L1
    float s;
    {
        float k = bestE; int h = 0;
        if (bestO < bestE) { k = bestO; h = 1; }
        int m2 = (int)(__float_as_uint(k) & 1023u);
        const float* Af = (const float*)&sA[m2];
        const float* Bf = (const float*)&sB[m2];
        float w0 = -0.5f * Af[h];
        float w1 = -0.5f * Af[2 + h];
        float w2 = -0.5f * Bf[h];
        s = sl1(xv.x, w0) + sl1(xv.y, w1) + sl1(xv.z, w2);
    }

    // ---- Reductions (CTA == tile) ----
    float S   = blockReduceSum(s, red);
    float sx0 = blockReduceSum(xv.x, red);
    float sx1 = blockReduceSum(xv.y, red);
    float sx2 = blockReduceSum(xv.z, red);
    float st0 = blockReduceSum(t0, red);
    float st1 = blockReduceSum(t1, red);
    float st2 = blockReduceSum(t2, red);

    if (tid == 0) {
        g_loss_part[bt] = W[bt] * S;
        float inv = 1.0f / (float)NPTS;
        g_lossc_part[bt] = sl1(sx0 * inv, st0 * inv)
                         + sl1(sx1 * inv, st1 * inv)
                         + sl1(sx2 * inv, st2 * inv);
        __threadfence();
        unsigned int prev = atomicAdd(&g_count, 1u);
        isLast = (prev == (unsigned int)(gridDim.x - 1)) ? 1 : 0;
    }
    __syncthreads();

    if (isLast && tid < 32) {
        __threadfence();
        float v1 = 0.0f, v2 = 0.0f;
        for (int i = tid; i < BT; i += 32) {
            v1 += g_loss_part[i];
            v2 += g_lossc_part[i];
        }
        #pragma unroll
        for (int o = 16; o > 0; o >>= 1) {
            v1 += __shfl_down_sync(0xffffffffu, v1, o);
            v2 += __shfl_down_sync(0xffffffffu, v2, o);
        }
        if (tid == 0) {
            out[0] = v1 / (3.0f * (float)NPTS * (float)B);
            out[1] = v2 / ((float)B * 3.0f);
            g_count = 0;
        }
    }
}

extern "C" void kernel_launch(void* const* d_in, const int* in_sizes, int n_in,
                              void* d_out, int out_size)
{
    const float* X = (const float*)d_in[0];   // [B,T,N,3]
    const float* T = (const float*)d_in[1];   // [B,T,N,3]
    const float* W = (const float*)d_in[2];   // [B,T]
    float* out = (float*)d_out;

    const int BT = in_sizes[2];               // 112
    const int B  = 4;

    size_t smem = (size_t)MAXPAIR * 2 * sizeof(float4)   // sA + sB
                + (size_t)NPTS * sizeof(float4)          // xs
                + (65 + 64 + 64) * sizeof(int)
                + 32 * sizeof(float);
    nn_loss_kernel<<<BT, NPTS, smem>>>(X, T, W, out, BT, B);
}

// round 14
// speedup vs baseline: 1.1405x; 1.1405x over previous
#include <cuda_runtime.h>
#include <math.h>
#include <float.h>

#define MAXBT 1024
__device__ float g_loss_part[MAXBT];
__device__ float g_lossc_part[MAXBT];
__device__ unsigned int g_count;

typedef unsigned long long u64;

#define NBINS 64
#define XMINV (-4.0f)
#define BINW  (0.125f)
#define INVW  (8.0f)
#define NPTS  1024
#define MAXPAIR 544   // (1024 + 64 pad) / 2

__device__ __forceinline__ u64 pk2(float lo, float hi) {
    u64 r; asm("mov.b64 %0, {%1,%2};" : "=l"(r) : "f"(lo), "f"(hi)); return r;
}
__device__ __forceinline__ void upk2(float& lo, float& hi, u64 v) {
    asm("mov.b64 {%0,%1}, %2;" : "=f"(lo), "=f"(hi) : "l"(v));
}
__device__ __forceinline__ u64 ffma2(u64 a, u64 b, u64 c) {
    u64 d; asm("fma.rn.f32x2 %0, %1, %2, %3;" : "=l"(d) : "l"(a), "l"(b), "l"(c)); return d;
}

__device__ __forceinline__ float sl1(float a, float b) {
    float d = fabsf(a - b);
    return d < 1.0f ? 0.5f * d * d : d - 0.5f;
}

// Embed low 10 bits (pair id) into a float key's truncated mantissa.
// Keys are d' = tn - 2 x.t (signed); FMNMX orders them correctly.
__device__ __forceinline__ float embed10(float d, unsigned m2) {
    return __uint_as_float((__float_as_uint(d) & 0xFFFFFC00u) | m2);
}

__device__ __forceinline__ float blockReduceSum(float v, float* red) {
    #pragma unroll
    for (int o = 16; o > 0; o >>= 1)
        v += __shfl_down_sync(0xffffffffu, v, o);
    int lane = threadIdx.x & 31;
    int wid  = threadIdx.x >> 5;
    __syncthreads();
    if (lane == 0) red[wid] = v;
    __syncthreads();
    if (wid == 0) {
        v = (lane < (int)(blockDim.x >> 5)) ? red[lane] : 0.0f;
        #pragma unroll
        for (int o = 16; o > 0; o >>= 1)
            v += __shfl_down_sync(0xffffffffu, v, o);
    }
    return v;
}

// One CTA per (b,t) tile, 1024 threads. Targets counting-sorted into 64 bins
// by tx (bins padded to even counts with tn=1e30 sentinels), paired layout:
//   sA[m2] = (-2tx_e, -2tx_o, -2ty_e, -2ty_o)
//   sB[m2] = (-2tz_e, -2tz_o,  tn_e,   tn_o)
// Preds bin-sorted too. Scan window is WARP-UNIFORM: the warp scans the
// contiguous pair range covering all lanes' bins, then expands left/right
// via __any_sync ballots (no divergent branches); pruning bound is exact:
// dist^2 >= (tx - xx)^2 at bin edges.
__global__ __launch_bounds__(1024, 1)
void nn_loss_kernel(const float* __restrict__ X,
                    const float* __restrict__ T,
                    const float* __restrict__ W,
                    float* __restrict__ out,
                    int BT, int B)
{
    extern __shared__ char smem[];
    float4* sA  = (float4*)smem;                              //  8704 B
    float4* sB  = sA + MAXPAIR;                               //  8704 B
    float4* xs  = sB + MAXPAIR;                               // 16384 B (sorted preds)
    int* binSt  = (int*)(xs + NPTS);                          // 65
    int* curT   = binSt + 65;                                 // 64
    int* curP   = curT + NBINS;                               // 64
    float* red  = (float*)(curP + NBINS);                     // 32
    __shared__ int isLast;

    const int bt  = blockIdx.x;
    const int tid = threadIdx.x;
    const float* Xb = X + (size_t)bt * NPTS * 3;
    const float* Tb = T + (size_t)bt * NPTS * 3;

    // ---- Stage 1: load, zero histograms, init sentinels ----
    float t0 = Tb[tid * 3 + 0], t1 = Tb[tid * 3 + 1], t2 = Tb[tid * 3 + 2];
    float x0 = Xb[tid * 3 + 0], x1 = Xb[tid * 3 + 1], x2 = Xb[tid * 3 + 2];
    float tn = fmaf(t0, t0, fmaf(t1, t1, t2 * t2));
    float xn = fmaf(x0, x0, fmaf(x1, x1, x2 * x2));

    if (tid < NBINS) curT[tid] = 0;
    else if (tid < 2 * NBINS) curP[tid - NBINS] = 0;
    for (int i = tid; i < MAXPAIR; i += NPTS) {
        sA[i] = make_float4(0.f, 0.f, 0.f, 0.f);
        sB[i] = make_float4(0.f, 0.f, 1e30f, 1e30f);
    }
    __syncthreads();

    int tbin = min(max((int)((t0 - XMINV) * INVW), 0), NBINS - 1);
    int pbin = min(max((int)((x0 - XMINV) * INVW), 0), NBINS - 1);
    atomicAdd(&curT[tbin], 1);
    atomicAdd(&curP[pbin], 1);
    __syncthreads();

    // ---- Stage 2: prefix sums (thread 0; even-rounded target bins) ----
    if (tid == 0) {
        int start = 0;
        #pragma unroll
        for (int b = 0; b < NBINS; ++b) {
            binSt[b] = start;
            start += (curT[b] + 1) & ~1;
        }
        binSt[NBINS] = start;
        int ps = 0;
        #pragma unroll
        for (int b = 0; b < NBINS; ++b) {
            int c = curP[b];
            curP[b] = ps;
            ps += c;
        }
        #pragma unroll
        for (int b = 0; b < NBINS; ++b) curT[b] = binSt[b];
    }
    __syncthreads();

    // ---- Stage 3: scatter ----
    {
        int slot = atomicAdd(&curT[tbin], 1);
        int m2 = slot >> 1, p = slot & 1;
        float* A  = (float*)&sA[m2];
        float* Bp = (float*)&sB[m2];
        A[p]      = -2.0f * t0;
        A[2 + p]  = -2.0f * t1;
        Bp[p]     = -2.0f * t2;
        Bp[2 + p] = tn;
        int ps = atomicAdd(&curP[pbin], 1);
        xs[ps] = make_float4(x0, x1, x2, xn);
    }
    __syncthreads();

    // ---- Stage 4: warp-uniform pruned scan ----
    float4 xv = xs[tid];
    float xx = xv.x, xn2 = xv.w;
    u64 X0 = pk2(xv.x, xv.x), X1 = pk2(xv.y, xv.y), X2 = pk2(xv.z, xv.z);
    const ulonglong2* pA = (const ulonglong2*)sA;
    const ulonglong2* pB = (const ulonglong2*)sB;

    float bestE = FLT_MAX, bestO = FLT_MAX;

    // Straight-line scan of a contiguous m2 range (warp-uniform bounds).
    auto scan_range = [&](int m2s, int m2e) {
        #pragma unroll 4
        for (int m2 = m2s; m2 < m2e; ++m2) {
            ulonglong2 a = pA[m2];
            ulonglong2 c = pB[m2];
            u64 dp = ffma2(X0, a.x, ffma2(X1, a.y, ffma2(X2, c.x, c.y)));
            float d0, d1;
            upk2(d0, d1, dp);
            bestE = fminf(bestE, embed10(d0, (unsigned)m2));
            bestO = fminf(bestO, embed10(d1, (unsigned)m2));
        }
    };

    {
        int myb = min(max((int)((xx - XMINV) * INVW), 0), NBINS - 1);
        // preds bin-sorted -> myb monotone within warp
        int wlo = __shfl_sync(0xffffffffu, myb, 0);
        int whi = __shfl_sync(0xffffffffu, myb, 31);

        scan_range(binSt[wlo] >> 1, binSt[whi + 1] >> 1);

        int r = whi + 1, l = wlo - 1;
        for (;;) {
            float bk = fminf(bestE, bestO);   // truncated best d' (<= true)
            bool needR = false, needL = false;
            if (r < NBINS) {
                float dx = fmaxf((XMINV + (float)r * BINW) - xx, 0.0f);
                needR = fmaf(dx, dx, -xn2) <= bk;
            }
            if (l >= 0) {
                float dx = fmaxf(xx - (XMINV + (float)(l + 1) * BINW), 0.0f);
                needL = fmaf(dx, dx, -xn2) <= bk;
            }
            bool anyR = __any_sync(0xffffffffu, needR) && (r < NBINS);
            bool anyL = __any_sync(0xffffffffu, needL) && (l >= 0);
            if (!anyR && !anyL) break;
            if (anyR) { scan_range(binSt[r] >> 1, binSt[r + 1] >> 1); ++r; }
            if (anyL) { scan_range(binSt[l] >> 1, binSt[l + 1] >> 1); --l; }
        }
    }

    // decode winner, gather coords, smooth-L1
    float s;
    {
        float k = bestE; int h = 0;
        if (bestO < bestE) { k = bestO; h = 1; }
        int m2 = (int)(__float_as_uint(k) & 1023u);
        const float* Af = (const float*)&sA[m2];
        const float* Bf = (const float*)&sB[m2];
        s = sl1(xv.x, -0.5f * Af[h])
          + sl1(xv.y, -0.5f * Af[2 + h])
          + sl1(xv.z, -0.5f * Bf[h]);
    }

    // ---- Reductions (CTA == tile) ----
    float S   = blockReduceSum(s, red);
    float sx0 = blockReduceSum(xv.x, red);
    float sx1 = blockReduceSum(xv.y, red);
    float sx2 = blockReduceSum(xv.z, red);
    float st0 = blockReduceSum(t0, red);
    float st1 = blockReduceSum(t1, red);
    float st2 = blockReduceSum(t2, red);

    if (tid == 0) {
        g_loss_part[bt] = W[bt] * S;
        float inv = 1.0f / (float)NPTS;
        g_lossc_part[bt] = sl1(sx0 * inv, st0 * inv)
                         + sl1(sx1 * inv, st1 * inv)
                         + sl1(sx2 * inv, st2 * inv);
        __threadfence();
        unsigned int prev = atomicAdd(&g_count, 1u);
        isLast = (prev == (unsigned int)(gridDim.x - 1)) ? 1 : 0;
    }
    __syncthreads();

    if (isLast && tid < 32) {
        __threadfence();
        float v1 = 0.0f, v2 = 0.0f;
        for (int i = tid; i < BT; i += 32) {
            v1 += g_loss_part[i];
            v2 += g_lossc_part[i];
        }
        #pragma unroll
        for (int o = 16; o > 0; o >>= 1) {
            v1 += __shfl_down_sync(0xffffffffu, v1, o);
            v2 += __shfl_down_sync(0xffffffffu, v2, o);
        }
        if (tid == 0) {
            out[0] = v1 / (3.0f * (float)NPTS * (float)B);
            out[1] = v2 / ((float)B * 3.0f);
            g_count = 0;
        }
    }
}

extern "C" void kernel_launch(void* const* d_in, const int* in_sizes, int n_in,
                              void* d_out, int out_size)
{
    const float* X = (const float*)d_in[0];   // [B,T,N,3]
    const float* T = (const float*)d_in[1];   // [B,T,N,3]
    const float* W = (const float*)d_in[2];   // [B,T]
    float* out = (float*)d_out;

    const int BT = in_sizes[2];               // 112
    const int B  = 4;

    size_t smem = (size_t)MAXPAIR * 2 * sizeof(float4)
                + (size_t)NPTS * sizeof(float4)
                + (65 + 64 + 64) * sizeof(int)
                + 32 * sizeof(float);
    nn_loss_kernel<<<BT, NPTS, smem>>>(X, T, W, out, BT, B);
}